// round 3
// baseline (speedup 1.0000x reference)
#include <cuda_runtime.h>

// ---------------------------------------------------------------------------
// LogicMachine (breadth=2, minmax, exclude_self, sigmoid), 3 layers.
// B=4, n=256, O=128. Layer dims: L0 in = (32,64,64); L1/L2 in = (128,128,128).
//
// o2[b,i,j] = sigmoid( P[b,i] + Q[b,j] + f2[b,i,j]·Wb + f2[b,j,i]·Wd )
//   with P = f1·Wa + b2, Q = f1·Wc   (Wa/Wb/Wc/Wd = row-slices of W2)
// ---------------------------------------------------------------------------

#define BD 4
#define NN 256
#define OO 128
#define JT 128          // j-tile for ord2
#define XS 130          // padded smem row stride for transposed X (conflict-free)

__device__ float g_f2a[(size_t)BD * NN * NN * 128];
__device__ float g_f2b[(size_t)BD * NN * NN * 128];
__device__ float g_f1a[BD * NN * 128];
__device__ float g_f1b[BD * NN * 128];
__device__ float g_f0a[BD * 128];
__device__ float g_f0b[BD * 128];
__device__ float g_r1[BD * 2 * 128];
__device__ float g_r2[BD * NN * 2 * 128];
__device__ float g_P[BD * NN * OO];
__device__ float g_Q[BD * NN * OO];

__device__ __forceinline__ float sigmoidf_(float x) {
    return 1.0f / (1.0f + __expf(-x));
}

// Packed f32x2 helpers (sm_100+ PTX).
__device__ __forceinline__ unsigned long long pk2(float x) {
    unsigned long long r;
    asm("mov.b64 %0, {%1, %1};" : "=l"(r) : "f"(x));
    return r;
}
__device__ __forceinline__ void fma2(unsigned long long& d,
                                     unsigned long long a,
                                     unsigned long long b) {
    asm("fma.rn.f32x2 %0, %1, %2, %0;" : "+l"(d) : "l"(a), "l"(b));
}
__device__ __forceinline__ float2 up2(unsigned long long v) {
    float2 r;
    asm("mov.b64 {%0, %1}, %2;" : "=f"(r.x), "=f"(r.y) : "l"(v));
    return r;
}

// ---------------------------------------------------------------------------
// Reductions
// ---------------------------------------------------------------------------
__global__ void k_reduce1(const float* __restrict__ f1, float* __restrict__ r1, int d1) {
    int b = blockIdx.x;
    int k = threadIdx.x;
    if (k >= d1) return;
    const float* p = f1 + (size_t)b * NN * d1 + k;
    float mx = -1e30f, mn = 1e30f;
    for (int i = 0; i < NN; i++) {
        float v = p[(size_t)i * d1];
        mx = fmaxf(mx, v);
        mn = fminf(mn, v);
    }
    r1[b * 2 * d1 + k] = mx;
    r1[b * 2 * d1 + d1 + k] = mn;
}

__global__ void k_reduce2(const float* __restrict__ f2, float* __restrict__ r2, int d2) {
    int bi = blockIdx.x;               // b*NN + i
    int i = bi % NN;
    int k = threadIdx.x;
    if (k >= d2) return;
    const float* p = f2 + (size_t)bi * NN * d2 + k;
    float mx = -1e30f, mn = 1e30f;
    for (int j = 0; j < NN; j++) {
        float v = p[(size_t)j * d2];
        float vm = (j == i) ? 0.0f : v;
        float vn = (j == i) ? 1.0f : v;
        mx = fmaxf(mx, vm);
        mn = fminf(mn, vn);
    }
    r2[(size_t)bi * 2 * d2 + k] = mx;
    r2[(size_t)bi * 2 * d2 + d2 + k] = mn;
}

// ---------------------------------------------------------------------------
// Order 0 (trivial)
// ---------------------------------------------------------------------------
__global__ void k_ord0(const float* __restrict__ f0, const float* __restrict__ r1,
                       const float* __restrict__ W, const float* __restrict__ bias,
                       float* __restrict__ out, int d0, int d1) {
    __shared__ float sg[384];
    int b = blockIdx.x, t = threadIdx.x;
    for (int idx = t; idx < d0; idx += blockDim.x) sg[idx] = f0[b * d0 + idx];
    for (int idx = t; idx < 2 * d1; idx += blockDim.x) sg[d0 + idx] = r1[b * 2 * d1 + idx];
    __syncthreads();
    int K = d0 + 2 * d1;
    float acc = bias[t];
    for (int k = 0; k < K; k++) acc += sg[k] * W[k * OO + t];
    out[b * OO + t] = sigmoidf_(acc);
}

// ---------------------------------------------------------------------------
// Order 1: 4 rows per block -> 4x less W traffic from L2
// ---------------------------------------------------------------------------
__global__ __launch_bounds__(128) void k_ord1(
    const float* __restrict__ f0, const float* __restrict__ f1,
    const float* __restrict__ r2,
    const float* __restrict__ W, const float* __restrict__ bias,
    float* __restrict__ out, int d0, int d1, int d2) {
    __shared__ float sg[4][512];
    int bi0 = blockIdx.x * 4;
    int b = bi0 / NN;
    int t = threadIdx.x;
    int K = d0 + d1 + 2 * d2;
    for (int r = 0; r < 4; r++) {
        int bi = bi0 + r;
        for (int idx = t; idx < d0; idx += 128) sg[r][idx] = f0[b * d0 + idx];
        for (int idx = t; idx < d1; idx += 128) sg[r][d0 + idx] = f1[(size_t)bi * d1 + idx];
        for (int idx = t; idx < 2 * d2; idx += 128)
            sg[r][d0 + d1 + idx] = r2[(size_t)bi * 2 * d2 + idx];
    }
    __syncthreads();
    float acc0 = bias[t], acc1 = acc0, acc2 = acc0, acc3 = acc0;
#pragma unroll 4
    for (int k = 0; k < K; k++) {
        float wv = __ldg(W + k * OO + t);
        acc0 += sg[0][k] * wv;
        acc1 += sg[1][k] * wv;
        acc2 += sg[2][k] * wv;
        acc3 += sg[3][k] * wv;
    }
    out[(size_t)(bi0 + 0) * OO + t] = sigmoidf_(acc0);
    out[(size_t)(bi0 + 1) * OO + t] = sigmoidf_(acc1);
    out[(size_t)(bi0 + 2) * OO + t] = sigmoidf_(acc2);
    out[(size_t)(bi0 + 3) * OO + t] = sigmoidf_(acc3);
}

// ---------------------------------------------------------------------------
// P/Q precompute: 4 rows per block
// ---------------------------------------------------------------------------
__global__ __launch_bounds__(128) void k_pq(
    const float* __restrict__ f1, const float* __restrict__ W2,
    const float* __restrict__ b2,
    float* __restrict__ P, float* __restrict__ Q, int d1, int d2) {
    __shared__ float sf[4][128];
    int bi0 = blockIdx.x * 4;
    int t = threadIdx.x;
    for (int r = 0; r < 4; r++)
        for (int idx = t; idx < d1; idx += 128) sf[r][idx] = f1[(size_t)(bi0 + r) * d1 + idx];
    __syncthreads();
    const float* Wa = W2;
    const float* Wc = W2 + (size_t)(d1 + d2) * OO;
    float bv = b2[t];
    float p0 = bv, p1 = bv, p2 = bv, p3 = bv;
    float q0 = 0, q1 = 0, q2 = 0, q3 = 0;
#pragma unroll 4
    for (int k = 0; k < d1; k++) {
        float wa = __ldg(Wa + k * OO + t);
        float wc = __ldg(Wc + k * OO + t);
        p0 += sf[0][k] * wa; q0 += sf[0][k] * wc;
        p1 += sf[1][k] * wa; q1 += sf[1][k] * wc;
        p2 += sf[2][k] * wa; q2 += sf[2][k] * wc;
        p3 += sf[3][k] * wa; q3 += sf[3][k] * wc;
    }
    P[(size_t)(bi0 + 0) * OO + t] = p0; Q[(size_t)(bi0 + 0) * OO + t] = q0;
    P[(size_t)(bi0 + 1) * OO + t] = p1; Q[(size_t)(bi0 + 1) * OO + t] = q1;
    P[(size_t)(bi0 + 2) * OO + t] = p2; Q[(size_t)(bi0 + 2) * OO + t] = q2;
    P[(size_t)(bi0 + 3) * OO + t] = p3; Q[(size_t)(bi0 + 3) * OO + t] = q3;
}

// ---------------------------------------------------------------------------
// Order 2. Grid (BD*NN, 2). 512 threads (16 warps, 4/SMSP).
// Block = (b,i) x o-half (64 cols). j-tile = 128.
// X staged TRANSPOSED in smem ([k][j], stride XS=130) so adjacent-j pairs are
// a single 8B broadcast load used directly as the f32x2 multiplier; only the
// weight scalar is splatted (amortized over 4 j-pairs).
// Thread: 4 j-pairs (8 rows, rows warp*8..+7) x 2 output cols (lane*2).
// ---------------------------------------------------------------------------
template <int D2>
__device__ __forceinline__ void mac_pass(const float* __restrict__ sW,
                                         const float* __restrict__ sX,
                                         int j0, int ol,
                                         unsigned long long (&acc)[4][2]) {
#pragma unroll 2
    for (int k = 0; k < D2; k += 4) {
        unsigned long long wv[4];
#pragma unroll
        for (int q = 0; q < 4; q++)
            wv[q] = *(const unsigned long long*)(sW + (k + q) * 64 + ol);
#pragma unroll
        for (int q = 0; q < 4; q++) {
            float2 w2 = up2(wv[q]);
            unsigned long long w0 = pk2(w2.x);
            unsigned long long w1 = pk2(w2.y);
#pragma unroll
            for (int p = 0; p < 4; p++) {
                unsigned long long xp =
                    *(const unsigned long long*)(sX + (k + q) * XS + j0 + 2 * p);
                fma2(acc[p][0], xp, w0);
                fma2(acc[p][1], xp, w1);
            }
        }
    }
}

template <int D2>
__global__ __launch_bounds__(512) void k_ord2(
    const float* __restrict__ f2,
    const float* __restrict__ Wb, const float* __restrict__ Wd,
    const float* __restrict__ P, const float* __restrict__ Q,
    float* __restrict__ out) {
    extern __shared__ float sm[];
    float* sWb = sm;                    // D2*64
    float* sWd = sWb + D2 * 64;         // D2*64
    float* sXa = sWd + D2 * 64;         // D2*XS  (transposed [k][j])
    float* sXb = sXa + D2 * XS;         // D2*XS
    float* sP  = sXb + D2 * XS;         // 64

    int t = threadIdx.x;
    int bi = blockIdx.x;
    int b = bi >> 8, i = bi & 255;
    int ob0 = blockIdx.y * 64;

    // Stage this o-half's weight slices.
    for (int idx = t; idx < D2 * 16; idx += 512) {
        int r = idx >> 4, c = (idx & 15) << 2;
        *(float4*)(sWb + r * 64 + c) = *(const float4*)(Wb + r * OO + ob0 + c);
        *(float4*)(sWd + r * 64 + c) = *(const float4*)(Wd + r * OO + ob0 + c);
    }
    if (t < 64) sP[t] = P[(size_t)bi * OO + ob0 + t];

    int warp = t >> 5, lane = t & 31;
    int j0 = warp * 8;      // 8 j-rows per warp
    int ol = lane * 2;      // 2 cols per lane (local)

    const float* f2i = f2 + (size_t)bi * (NN * D2);

    for (int jt = 0; jt < NN; jt += JT) {
        __syncthreads();
        // Load + transpose Xa (contiguous rows) and Xb (gathered rows).
        {
            int j = t >> 2, kq = (t & 3) << 2;
            const float* srcA = f2i + (size_t)(jt + j) * D2;
            const float* srcB = f2 + ((size_t)(b * NN + jt + j) * NN + i) * D2;
#pragma unroll
            for (int kb = 0; kb < D2; kb += 16) {
                int k = kb + kq;
                float4 va = *(const float4*)(srcA + k);
                float4 vb = *(const float4*)(srcB + k);
                sXa[(k + 0) * XS + j] = va.x;
                sXa[(k + 1) * XS + j] = va.y;
                sXa[(k + 2) * XS + j] = va.z;
                sXa[(k + 3) * XS + j] = va.w;
                sXb[(k + 0) * XS + j] = vb.x;
                sXb[(k + 1) * XS + j] = vb.y;
                sXb[(k + 2) * XS + j] = vb.z;
                sXb[(k + 3) * XS + j] = vb.w;
            }
        }
        __syncthreads();

        unsigned long long acc[4][2];
#pragma unroll
        for (int p = 0; p < 4; p++) { acc[p][0] = 0ull; acc[p][1] = 0ull; }

        mac_pass<D2>(sWb, sXa, j0, ol, acc);
        mac_pass<D2>(sWd, sXb, j0, ol, acc);

        // Epilogue: acc[p][o] packs rows (j0+2p, j0+2p+1) at col ol+o.
        float pc0 = sP[ol], pc1 = sP[ol + 1];
#pragma unroll
        for (int p = 0; p < 4; p++) {
            float2 a0 = up2(acc[p][0]);   // col ol,   rows (r0, r0+1)
            float2 a1 = up2(acc[p][1]);   // col ol+1, rows (r0, r0+1)
            int r0 = jt + j0 + 2 * p;
            const float* qb = Q + ((size_t)(b * NN) + r0) * OO + ob0 + ol;
            float2 q0 = *(const float2*)(qb);
            float2 q1 = *(const float2*)(qb + OO);
            float2 o0, o1;
            o0.x = sigmoidf_(pc0 + q0.x + a0.x);
            o0.y = sigmoidf_(pc1 + q0.y + a1.x);
            o1.x = sigmoidf_(pc0 + q1.x + a0.y);
            o1.y = sigmoidf_(pc1 + q1.y + a1.y);
            float* ob = out + ((size_t)bi * NN + r0) * OO + ob0 + ol;
            *(float2*)(ob) = o0;
            *(float2*)(ob + OO) = o1;
        }
    }
}

// ---------------------------------------------------------------------------
// Host side
// ---------------------------------------------------------------------------
static inline size_t smem_ord2(int d2) {
    return (size_t)(2 * d2 * 64 + 2 * d2 * XS + 64) * sizeof(float);
}

extern "C" void kernel_launch(void* const* d_in, const int* in_sizes, int n_in,
                              void* d_out, int out_size) {
    const float* x0 = (const float*)d_in[0];
    const float* x1 = (const float*)d_in[1];
    const float* x2 = (const float*)d_in[2];
    const float* Wt[3][3];
    const float* bt[3][3];
    for (int l = 0; l < 3; l++)
        for (int o = 0; o < 3; o++) {
            Wt[l][o] = (const float*)d_in[3 + l * 6 + o * 2];
            bt[l][o] = (const float*)d_in[3 + l * 6 + o * 2 + 1];
        }

    float *f2a, *f2b, *f1a, *f1b, *f0a, *f0b, *r1, *r2, *P, *Q;
    cudaGetSymbolAddress((void**)&f2a, g_f2a);
    cudaGetSymbolAddress((void**)&f2b, g_f2b);
    cudaGetSymbolAddress((void**)&f1a, g_f1a);
    cudaGetSymbolAddress((void**)&f1b, g_f1b);
    cudaGetSymbolAddress((void**)&f0a, g_f0a);
    cudaGetSymbolAddress((void**)&f0b, g_f0b);
    cudaGetSymbolAddress((void**)&r1, g_r1);
    cudaGetSymbolAddress((void**)&r2, g_r2);
    cudaGetSymbolAddress((void**)&P, g_P);
    cudaGetSymbolAddress((void**)&Q, g_Q);

    float* out = (float*)d_out;
    float* o0_f = out;
    float* o1_f = out + BD * OO;
    float* o2_f = out + BD * OO + (size_t)BD * NN * OO;

    cudaFuncSetAttribute(k_ord2<64>, cudaFuncAttributeMaxDynamicSharedMemorySize,
                         (int)smem_ord2(64));
    cudaFuncSetAttribute(k_ord2<128>, cudaFuncAttributeMaxDynamicSharedMemorySize,
                         (int)smem_ord2(128));

    struct L {
        const float *f0, *f1, *f2;
        float *o0, *o1, *o2;
        int d0, d1, d2;
    };
    L Ls[3] = {
        { x0,  x1,  x2,  f0a,  f1a,  f2a,  32,  64,  64 },
        { f0a, f1a, f2a, f0b,  f1b,  f2b,  128, 128, 128 },
        { f0b, f1b, f2b, o0_f, o1_f, o2_f, 128, 128, 128 },
    };

    for (int l = 0; l < 3; l++) {
        const L& a = Ls[l];
        k_reduce1<<<BD, 128>>>(a.f1, r1, a.d1);
        k_reduce2<<<BD * NN, 128>>>(a.f2, r2, a.d2);
        k_ord0<<<BD, 128>>>(a.f0, r1, Wt[l][0], bt[l][0], a.o0, a.d0, a.d1);
        k_ord1<<<BD * NN / 4, 128>>>(a.f0, a.f1, r2, Wt[l][1], bt[l][1], a.o1,
                                     a.d0, a.d1, a.d2);
        k_pq<<<BD * NN / 4, 128>>>(a.f1, Wt[l][2], bt[l][2], P, Q, a.d1, a.d2);
        const float* Wb = Wt[l][2] + (size_t)a.d1 * OO;
        const float* Wd = Wt[l][2] + (size_t)(2 * a.d1 + a.d2) * OO;
        dim3 grid(BD * NN, 2);
        if (a.d2 == 64)
            k_ord2<64><<<grid, 512, smem_ord2(64)>>>(a.f2, Wb, Wd, P, Q, a.o2);
        else
            k_ord2<128><<<grid, 512, smem_ord2(128)>>>(a.f2, Wb, Wd, P, Q, a.o2);
    }
}

// round 9
// speedup vs baseline: 1.2944x; 1.2944x over previous
#include <cuda_runtime.h>
#include <cuda_bf16.h>
#include <cstdint>

// ---------------------------------------------------------------------------
// LogicMachine (breadth=2, minmax, exclude_self, sigmoid), 3 layers.
// B=4, n=256, O=128. Layer dims: L0 in = (32,64,64); L1/L2 in = (128,128,128).
//
// o2[b,i,j] = sigmoid( P[b,i] + Q[b,j] + f2[b,i,j]·Wb + f2[b,j,i]·Wd )
//   with P = f1·Wa + b2, Q = f1·Wc   (Wa/Wb/Wc/Wd = row-slices of W2)
//
// ord2 via mma.sync.m16n8k16.bf16 (base-target PTX; harness compiles sm_103
// non-'a' so tcgen05 is unavailable). 3-term bf16 hi/lo compensation:
//   x·w ≈ xh·wh + xh·wl + xl·wh  (fp32 accumulate)
// f2 is carried between layers as bf16 (hi,lo) pairs.
// ---------------------------------------------------------------------------

#define BD 4
#define NN 256
#define OO 128

// Inter-layer buffers.
__device__ __nv_bfloat16 g_h0[(size_t)BD * NN * NN * 128];
__device__ __nv_bfloat16 g_l0[(size_t)BD * NN * NN * 128];
__device__ __nv_bfloat16 g_h1[(size_t)BD * NN * NN * 128];
__device__ __nv_bfloat16 g_l1[(size_t)BD * NN * NN * 128];
__device__ __nv_bfloat16 g_ws[4 * 128 * 136];       // W scratch [4][128][D2+8]
__device__ float g_f1a[BD * NN * 128];
__device__ float g_f1b[BD * NN * 128];
__device__ float g_f0a[BD * 128];
__device__ float g_f0b[BD * 128];
__device__ float g_r1[BD * 2 * 128];
__device__ float g_r2[BD * NN * 2 * 128];
__device__ float g_P[BD * NN * OO];
__device__ float g_Q[BD * NN * OO];

__device__ __forceinline__ float sigmoidf_(float x) {
    return 1.0f / (1.0f + __expf(-x));
}

__device__ __forceinline__ uint32_t smem_u32(const void* p) {
    uint32_t a;
    asm("{ .reg .u64 t; cvta.to.shared.u64 t, %1; cvt.u32.u64 %0, t; }"
        : "=r"(a) : "l"(p));
    return a;
}
__device__ __forceinline__ void cpa16(uint32_t dst, const void* src) {
    asm volatile("cp.async.cg.shared.global [%0], [%1], 16;" :: "r"(dst), "l"(src));
}
__device__ __forceinline__ void cpcommit() {
    asm volatile("cp.async.commit_group;" ::: "memory");
}
__device__ __forceinline__ void cpwait1() {
    asm volatile("cp.async.wait_group 1;" ::: "memory");
}
__device__ __forceinline__ void cpwait0() {
    asm volatile("cp.async.wait_group 0;" ::: "memory");
}

#define MMA_B16(d, a, b) \
    asm volatile( \
        "mma.sync.aligned.m16n8k16.row.col.f32.bf16.bf16.f32 " \
        "{%0,%1,%2,%3}, {%4,%5,%6,%7}, {%8,%9}, {%0,%1,%2,%3};" \
        : "+f"((d)[0]), "+f"((d)[1]), "+f"((d)[2]), "+f"((d)[3]) \
        : "r"((a)[0]), "r"((a)[1]), "r"((a)[2]), "r"((a)[3]), \
          "r"((b)[0]), "r"((b)[1]))

// ---------------------------------------------------------------------------
// Conversions
// ---------------------------------------------------------------------------
__global__ void k_xconv(const float4* __restrict__ x,
                        __nv_bfloat16* __restrict__ h,
                        __nv_bfloat16* __restrict__ l, int n4) {
    int idx = blockIdx.x * blockDim.x + threadIdx.x;
    if (idx >= n4) return;
    float4 v = x[idx];
    __nv_bfloat16 h0 = __float2bfloat16(v.x), h1 = __float2bfloat16(v.y);
    __nv_bfloat16 h2 = __float2bfloat16(v.z), h3 = __float2bfloat16(v.w);
    __nv_bfloat162* hp = (__nv_bfloat162*)(h + (size_t)idx * 4);
    __nv_bfloat162* lp = (__nv_bfloat162*)(l + (size_t)idx * 4);
    hp[0] = __nv_bfloat162(h0, h1);
    hp[1] = __nv_bfloat162(h2, h3);
    lp[0] = __nv_bfloat162(__float2bfloat16(v.x - __bfloat162float(h0)),
                           __float2bfloat16(v.y - __bfloat162float(h1)));
    lp[1] = __nv_bfloat162(__float2bfloat16(v.z - __bfloat162float(h2)),
                           __float2bfloat16(v.w - __bfloat162float(h3)));
}

// W scratch: [4][128 o][d2+8 k]: v0=Wb_h, v1=Wb_l, v2=Wd_h, v3=Wd_l.
__global__ void k_wconv(const float* __restrict__ Wb, const float* __restrict__ Wd,
                        __nv_bfloat16* __restrict__ ws, int d2) {
    int o = blockIdx.x;
    int wr = d2 + 8;
    for (int k = threadIdx.x; k < d2; k += blockDim.x) {
        float vb = Wb[(size_t)k * OO + o];
        float vd = Wd[(size_t)k * OO + o];
        __nv_bfloat16 hb = __float2bfloat16(vb);
        __nv_bfloat16 lb = __float2bfloat16(vb - __bfloat162float(hb));
        __nv_bfloat16 hd = __float2bfloat16(vd);
        __nv_bfloat16 ld2 = __float2bfloat16(vd - __bfloat162float(hd));
        ws[(size_t)(0 * 128 + o) * wr + k] = hb;
        ws[(size_t)(1 * 128 + o) * wr + k] = lb;
        ws[(size_t)(2 * 128 + o) * wr + k] = hd;
        ws[(size_t)(3 * 128 + o) * wr + k] = ld2;
    }
}

// ---------------------------------------------------------------------------
// Reductions
// ---------------------------------------------------------------------------
__global__ void k_reduce1(const float* __restrict__ f1, float* __restrict__ r1, int d1) {
    int b = blockIdx.x;
    int k = threadIdx.x;
    if (k >= d1) return;
    const float* p = f1 + (size_t)b * NN * d1 + k;
    float mx = -1e30f, mn = 1e30f;
    for (int i = 0; i < NN; i++) {
        float v = p[(size_t)i * d1];
        mx = fmaxf(mx, v);
        mn = fminf(mn, v);
    }
    r1[b * 2 * d1 + k] = mx;
    r1[b * 2 * d1 + d1 + k] = mn;
}

__global__ void k_reduce2b(const __nv_bfloat16* __restrict__ Xh,
                           const __nv_bfloat16* __restrict__ Xl,
                           float* __restrict__ r2, int d2) {
    int bi = blockIdx.x;
    int i = bi & 255;
    int k = threadIdx.x;
    if (k >= d2) return;
    const __nv_bfloat16* ph = Xh + (size_t)bi * NN * d2 + k;
    const __nv_bfloat16* pl = Xl + (size_t)bi * NN * d2 + k;
    float mx = -1e30f, mn = 1e30f;
    for (int j = 0; j < NN; j++) {
        float v = __bfloat162float(ph[(size_t)j * d2]) +
                  __bfloat162float(pl[(size_t)j * d2]);
        float vm = (j == i) ? 0.0f : v;
        float vn = (j == i) ? 1.0f : v;
        mx = fmaxf(mx, vm);
        mn = fminf(mn, vn);
    }
    r2[(size_t)bi * 2 * d2 + k] = mx;
    r2[(size_t)bi * 2 * d2 + d2 + k] = mn;
}

// ---------------------------------------------------------------------------
// Order 0
// ---------------------------------------------------------------------------
__global__ void k_ord0(const float* __restrict__ f0, const float* __restrict__ r1,
                       const float* __restrict__ W, const float* __restrict__ bias,
                       float* __restrict__ out, int d0, int d1) {
    __shared__ float sg[384];
    int b = blockIdx.x, t = threadIdx.x;
    for (int idx = t; idx < d0; idx += blockDim.x) sg[idx] = f0[b * d0 + idx];
    for (int idx = t; idx < 2 * d1; idx += blockDim.x) sg[d0 + idx] = r1[b * 2 * d1 + idx];
    __syncthreads();
    int K = d0 + 2 * d1;
    float acc = bias[t];
    for (int k = 0; k < K; k++) acc += sg[k] * W[k * OO + t];
    out[b * OO + t] = sigmoidf_(acc);
}

// ---------------------------------------------------------------------------
// Order 1: 16 rows per block
// ---------------------------------------------------------------------------
__global__ __launch_bounds__(128) void k_ord1(
    const float* __restrict__ f0, const float* __restrict__ f1,
    const float* __restrict__ r2,
    const float* __restrict__ W, const float* __restrict__ bias,
    float* __restrict__ out, int d0, int d1, int d2) {
    __shared__ float sg[16][512];
    int bi0 = blockIdx.x * 16;
    int b = bi0 / NN;
    int t = threadIdx.x;
    int K = d0 + d1 + 2 * d2;
    for (int r = 0; r < 16; r++) {
        int bi = bi0 + r;
        for (int idx = t; idx < d0; idx += 128) sg[r][idx] = f0[b * d0 + idx];
        for (int idx = t; idx < d1; idx += 128) sg[r][d0 + idx] = f1[(size_t)bi * d1 + idx];
        for (int idx = t; idx < 2 * d2; idx += 128)
            sg[r][d0 + d1 + idx] = r2[(size_t)bi * 2 * d2 + idx];
    }
    __syncthreads();
    float acc[16];
    float bv = bias[t];
#pragma unroll
    for (int r = 0; r < 16; r++) acc[r] = bv;
#pragma unroll 4
    for (int k = 0; k < K; k++) {
        float wv = __ldg(W + k * OO + t);
#pragma unroll
        for (int r = 0; r < 16; r++) acc[r] += sg[r][k] * wv;
    }
#pragma unroll
    for (int r = 0; r < 16; r++)
        out[(size_t)(bi0 + r) * OO + t] = sigmoidf_(acc[r]);
}

// ---------------------------------------------------------------------------
// P/Q precompute: 16 rows per block
// ---------------------------------------------------------------------------
__global__ __launch_bounds__(128) void k_pq(
    const float* __restrict__ f1, const float* __restrict__ W2,
    const float* __restrict__ b2,
    float* __restrict__ P, float* __restrict__ Q, int d1, int d2) {
    __shared__ float sf[16][128];
    int bi0 = blockIdx.x * 16;
    int t = threadIdx.x;
    for (int r = 0; r < 16; r++)
        for (int idx = t; idx < d1; idx += 128)
            sf[r][idx] = f1[(size_t)(bi0 + r) * d1 + idx];
    __syncthreads();
    const float* Wa = W2;
    const float* Wc = W2 + (size_t)(d1 + d2) * OO;
    float bv = b2[t];
    float pa[16], qa[16];
#pragma unroll
    for (int r = 0; r < 16; r++) { pa[r] = bv; qa[r] = 0.0f; }
#pragma unroll 4
    for (int k = 0; k < d1; k++) {
        float wa = __ldg(Wa + k * OO + t);
        float wc = __ldg(Wc + k * OO + t);
#pragma unroll
        for (int r = 0; r < 16; r++) {
            pa[r] += sf[r][k] * wa;
            qa[r] += sf[r][k] * wc;
        }
    }
#pragma unroll
    for (int r = 0; r < 16; r++) {
        P[(size_t)(bi0 + r) * OO + t] = pa[r];
        Q[(size_t)(bi0 + r) * OO + t] = qa[r];
    }
}

// ---------------------------------------------------------------------------
// Order 2 via mma.sync. Grid (1024 bi, 2 j-half). 256 threads, 8 warps (2x4).
// Block tile 128(j) x 128(o); warp tile 64x32; thread acc 4x4 m16n8 tiles.
// W: 4 variants resident in smem [o][d2+8] bf16 (from g_ws via cp.async).
// X: chunks of 32 k, (h,l) variants, rows at 96B stride, 2-stage cp.async.
// ---------------------------------------------------------------------------
template <int D2>
__device__ __forceinline__ void stageX(uint32_t dstBase,
                                       const __nv_bfloat16* __restrict__ Xh,
                                       const __nv_bfloat16* __restrict__ Xl,
                                       int chunk, int bi, int b, int i, int jb, int t) {
    constexpr int NC2 = D2 / 32;
    const bool sa = chunk < NC2;
    const int kc = (sa ? chunk : chunk - NC2) * 32;
#pragma unroll
    for (int s = 0; s < 4; s++) {
        int idx = t + s * 256;          // 0..1023
        int v = idx >> 9;               // variant (h/l)
        int r = (idx >> 2) & 127;       // row
        int u = idx & 3;                // 16B unit
        const __nv_bfloat16* src = v ? Xl : Xh;
        size_t row = sa ? ((size_t)bi * NN + (jb + r))
                        : ((size_t)(b * NN + jb + r) * NN + i);
        const void* gp = (const char*)(src + row * D2 + kc) + u * 16;
        cpa16(dstBase + v * (128 * 96) + r * 96 + u * 16, gp);
    }
}

template <int D2>
__device__ __forceinline__ void computeChunk(
    const char* __restrict__ sW, const char* __restrict__ sXs,
    bool sa, int kc, int wm, int wn, int g, int tig, float acc[4][4][4]) {
    constexpr int WR2 = (D2 + 8) * 2;
    const char* wh = sW + (size_t)(sa ? 0 : 2) * (128 * WR2);
    const char* wl = sW + (size_t)(sa ? 1 : 3) * (128 * WR2);
    const char* xh = sXs;
    const char* xl = sXs + 128 * 96;
#pragma unroll
    for (int ks = 0; ks < 2; ks++) {
        int kg = kc + ks * 16;
        int c0 = (ks * 16 + 2 * tig) * 2;
        int c8 = c0 + 16;
        uint32_t bwh[4][2], bwl[4][2];
#pragma unroll
        for (int nt = 0; nt < 4; nt++) {
            int orow = wn * 32 + nt * 8 + g;
            const char* ph = wh + orow * WR2 + (kg + 2 * tig) * 2;
            const char* pl = wl + orow * WR2 + (kg + 2 * tig) * 2;
            bwh[nt][0] = *(const uint32_t*)(ph);
            bwh[nt][1] = *(const uint32_t*)(ph + 16);
            bwl[nt][0] = *(const uint32_t*)(pl);
            bwl[nt][1] = *(const uint32_t*)(pl + 16);
        }
#pragma unroll
        for (int mt = 0; mt < 4; mt++) {
            int r0 = wm * 64 + mt * 16 + g;
            uint32_t axh[4], axl[4];
            axh[0] = *(const uint32_t*)(xh + r0 * 96 + c0);
            axh[1] = *(const uint32_t*)(xh + (r0 + 8) * 96 + c0);
            axh[2] = *(const uint32_t*)(xh + r0 * 96 + c8);
            axh[3] = *(const uint32_t*)(xh + (r0 + 8) * 96 + c8);
            axl[0] = *(const uint32_t*)(xl + r0 * 96 + c0);
            axl[1] = *(const uint32_t*)(xl + (r0 + 8) * 96 + c0);
            axl[2] = *(const uint32_t*)(xl + r0 * 96 + c8);
            axl[3] = *(const uint32_t*)(xl + (r0 + 8) * 96 + c8);
#pragma unroll
            for (int nt = 0; nt < 4; nt++) {
                MMA_B16(acc[mt][nt], axh, bwh[nt]);
                MMA_B16(acc[mt][nt], axh, bwl[nt]);
                MMA_B16(acc[mt][nt], axl, bwh[nt]);
            }
        }
    }
}

template <int D2, bool F32OUT>
__global__ __launch_bounds__(256) void k_ord2m(
    const __nv_bfloat16* __restrict__ Xh, const __nv_bfloat16* __restrict__ Xl,
    const __nv_bfloat16* __restrict__ Ws,
    const float* __restrict__ P, const float* __restrict__ Q,
    float* __restrict__ outF,
    __nv_bfloat16* __restrict__ Oh, __nv_bfloat16* __restrict__ Ol) {
    constexpr int NCH = 2 * (D2 / 32);
    constexpr int WR2 = (D2 + 8) * 2;
    constexpr int WBYTES = 4 * 128 * WR2;
    constexpr int XSTAGE = 2 * 128 * 96;
    extern __shared__ __align__(16) char smem[];
    char* sW = smem;
    char* sX = smem + WBYTES;
    float* sP = (float*)(smem + WBYTES + 2 * XSTAGE);

    int t = threadIdx.x;
    int bi = blockIdx.x, b = bi >> 8, i = bi & 255;
    int jb = blockIdx.y * 128;
    uint32_t sWu = smem_u32(smem);
    uint32_t sXu = sWu + WBYTES;

    // Stage W (linear copy from identically-laid-out scratch).
    {
        constexpr int WU = WBYTES / 16;
        const char* wsrc = (const char*)Ws;
        for (int u = t; u < WU; u += 256) cpa16(sWu + u * 16, wsrc + u * 16);
    }
    stageX<D2>(sXu, Xh, Xl, 0, bi, b, i, jb, t);
    cpcommit();
    stageX<D2>(sXu + XSTAGE, Xh, Xl, 1, bi, b, i, jb, t);
    cpcommit();
    if (t < 128) sP[t] = P[(size_t)bi * OO + t];

    int lane = t & 31, warp = t >> 5;
    int g = lane >> 2, tig = lane & 3;
    int wm = warp >> 2, wn = warp & 3;

    float acc[4][4][4];
#pragma unroll
    for (int a = 0; a < 4; a++)
#pragma unroll
        for (int c = 0; c < 4; c++)
#pragma unroll
            for (int d = 0; d < 4; d++) acc[a][c][d] = 0.0f;

#pragma unroll 1
    for (int c = 0; c < NCH; c++) {
        if (c + 1 < NCH) cpwait1(); else cpwait0();
        __syncthreads();
        bool sa = c < NCH / 2;
        int kc = (sa ? c : c - NCH / 2) * 32;
        computeChunk<D2>(sW, sX + (c & 1) * XSTAGE, sa, kc, wm, wn, g, tig, acc);
        __syncthreads();
        if (c + 2 < NCH) {
            stageX<D2>(sXu + (c & 1) * XSTAGE, Xh, Xl, c + 2, bi, b, i, jb, t);
            cpcommit();
        }
    }

    // Epilogue.
#pragma unroll
    for (int mt = 0; mt < 4; mt++) {
        int jl = wm * 64 + mt * 16 + g;
#pragma unroll
        for (int half = 0; half < 2; half++) {
            int j = jb + jl + half * 8;
            size_t rowq = ((size_t)(b * NN) + j) * OO;
            size_t rowo = ((size_t)bi * NN + j) * OO;
#pragma unroll
            for (int nt = 0; nt < 4; nt++) {
                int c = wn * 32 + nt * 8 + tig * 2;
                float a0 = acc[mt][nt][half * 2 + 0];
                float a1 = acc[mt][nt][half * 2 + 1];
                float2 q = *(const float2*)(Q + rowq + c);
                float v0 = sigmoidf_(sP[c] + q.x + a0);
                float v1 = sigmoidf_(sP[c + 1] + q.y + a1);
                if (F32OUT) {
                    float2 ov; ov.x = v0; ov.y = v1;
                    *(float2*)(outF + rowo + c) = ov;
                } else {
                    __nv_bfloat16 h0 = __float2bfloat16(v0);
                    __nv_bfloat16 h1 = __float2bfloat16(v1);
                    *(__nv_bfloat162*)(Oh + rowo + c) = __nv_bfloat162(h0, h1);
                    *(__nv_bfloat162*)(Ol + rowo + c) = __nv_bfloat162(
                        __float2bfloat16(v0 - __bfloat162float(h0)),
                        __float2bfloat16(v1 - __bfloat162float(h1)));
                }
            }
        }
    }
}

// ---------------------------------------------------------------------------
// Host side
// ---------------------------------------------------------------------------
static inline size_t smem_ord2m(int d2) {
    return (size_t)4 * 128 * (d2 + 8) * 2 + 2 * (2 * 128 * 96) + 512;
}

extern "C" void kernel_launch(void* const* d_in, const int* in_sizes, int n_in,
                              void* d_out, int out_size) {
    const float* x0 = (const float*)d_in[0];
    const float* x1 = (const float*)d_in[1];
    const float* x2 = (const float*)d_in[2];
    const float* Wt[3][3];
    const float* bt[3][3];
    for (int l = 0; l < 3; l++)
        for (int o = 0; o < 3; o++) {
            Wt[l][o] = (const float*)d_in[3 + l * 6 + o * 2];
            bt[l][o] = (const float*)d_in[3 + l * 6 + o * 2 + 1];
        }

    __nv_bfloat16 *h0, *l0, *h1, *l1, *ws;
    float *f1a, *f1b, *f0a, *f0b, *r1, *r2, *P, *Q;
    cudaGetSymbolAddress((void**)&h0, g_h0);
    cudaGetSymbolAddress((void**)&l0, g_l0);
    cudaGetSymbolAddress((void**)&h1, g_h1);
    cudaGetSymbolAddress((void**)&l1, g_l1);
    cudaGetSymbolAddress((void**)&ws, g_ws);
    cudaGetSymbolAddress((void**)&f1a, g_f1a);
    cudaGetSymbolAddress((void**)&f1b, g_f1b);
    cudaGetSymbolAddress((void**)&f0a, g_f0a);
    cudaGetSymbolAddress((void**)&f0b, g_f0b);
    cudaGetSymbolAddress((void**)&r1, g_r1);
    cudaGetSymbolAddress((void**)&r2, g_r2);
    cudaGetSymbolAddress((void**)&P, g_P);
    cudaGetSymbolAddress((void**)&Q, g_Q);

    float* out = (float*)d_out;
    float* o0_f = out;
    float* o1_f = out + BD * OO;
    float* o2_f = out + BD * OO + (size_t)BD * NN * OO;

    cudaFuncSetAttribute(k_ord2m<64, false>, cudaFuncAttributeMaxDynamicSharedMemorySize,
                         (int)smem_ord2m(64));
    cudaFuncSetAttribute(k_ord2m<128, false>, cudaFuncAttributeMaxDynamicSharedMemorySize,
                         (int)smem_ord2m(128));
    cudaFuncSetAttribute(k_ord2m<128, true>, cudaFuncAttributeMaxDynamicSharedMemorySize,
                         (int)smem_ord2m(128));

    // Convert x2 -> (h0, l0) once.
    {
        int n4 = BD * NN * NN * 64 / 4;
        k_xconv<<<(n4 + 255) / 256, 256>>>((const float4*)x2, h0, l0, n4);
    }

    struct L {
        const float* f0;
        const float* f1;
        const __nv_bfloat16 *xh, *xl;
        float *o0, *o1;
        __nv_bfloat16 *oh, *ol;
        float* of;
        int d0, d1, d2;
    };
    L Ls[3] = {
        { x0,  x1,  h0, l0, f0a,  f1a,  h1, l1, nullptr, 32,  64,  64 },
        { f0a, f1a, h1, l1, f0b,  f1b,  h0, l0, nullptr, 128, 128, 128 },
        { f0b, f1b, h0, l0, o0_f, o1_f, nullptr, nullptr, o2_f, 128, 128, 128 },
    };

    for (int l = 0; l < 3; l++) {
        const L& a = Ls[l];
        const float* Wb = Wt[l][2] + (size_t)a.d1 * OO;
        const float* Wd = Wt[l][2] + (size_t)(2 * a.d1 + a.d2) * OO;
        k_wconv<<<128, 128>>>(Wb, Wd, ws, a.d2);
        k_reduce1<<<BD, 128>>>(a.f1, r1, a.d1);
        k_reduce2b<<<BD * NN, 128>>>(a.xh, a.xl, r2, a.d2);
        k_ord0<<<BD, 128>>>(a.f0, r1, Wt[l][0], bt[l][0], a.o0, a.d0, a.d1);
        k_ord1<<<BD * NN / 16, 128>>>(a.f0, a.f1, r2, Wt[l][1], bt[l][1], a.o1,
                                      a.d0, a.d1, a.d2);
        k_pq<<<BD * NN / 16, 128>>>(a.f1, Wt[l][2], bt[l][2], P, Q, a.d1, a.d2);
        dim3 grid(BD * NN, 2);
        if (a.d2 == 64)
            k_ord2m<64, false><<<grid, 256, smem_ord2m(64)>>>(
                a.xh, a.xl, ws, P, Q, nullptr, a.oh, a.ol);
        else if (l == 2)
            k_ord2m<128, true><<<grid, 256, smem_ord2m(128)>>>(
                a.xh, a.xl, ws, P, Q, a.of, nullptr, nullptr);
        else
            k_ord2m<128, false><<<grid, 256, smem_ord2m(128)>>>(
                a.xh, a.xl, ws, P, Q, nullptr, a.oh, a.ol);
    }
}

// round 12
// speedup vs baseline: 1.4828x; 1.1456x over previous
#include <cuda_runtime.h>
#include <cuda_bf16.h>
#include <cstdint>

// ---------------------------------------------------------------------------
// LogicMachine (breadth=2, minmax, exclude_self, sigmoid), 3 layers.
// B=4, n=256, O=128. Layer dims: L0 in = (32,64,64); L1/L2 in = (128,128,128).
//
// o2[b,i,j] = sigmoid( P[b,i] + Q[b,j] + f2[b,i,j]·Wb + f2[b,j,i]·Wd )
//   with P = f1·Wa + b2, Q = f1·Wc   (Wa/Wb/Wc/Wd = row-slices of W2)
//
// ord2 via mma.sync.m16n8k16.bf16 (base-target PTX). 3-term bf16 hi/lo
// compensation: x·w ≈ xh·wh + xh·wl + xl·wh (fp32 accumulate).
// f2 carried between layers as bf16 (hi,lo) pairs.
// R10: 512 threads (4 warps/SMSP), 3-stage cp.async pipeline, 112B X stride
// (conflict-free), ord2m<64> moved to 4th launch for ncu capture.
// ---------------------------------------------------------------------------

#define BD 4
#define NN 256
#define OO 128
#define XRS 112   // X smem row stride in bytes (28 words: conflict-free)

// Inter-layer buffers.
__device__ __nv_bfloat16 g_h0[(size_t)BD * NN * NN * 128];
__device__ __nv_bfloat16 g_l0[(size_t)BD * NN * NN * 128];
__device__ __nv_bfloat16 g_h1[(size_t)BD * NN * NN * 128];
__device__ __nv_bfloat16 g_l1[(size_t)BD * NN * NN * 128];
__device__ __nv_bfloat16 g_ws[4 * 128 * 136];       // W scratch [4][128][D2+8]
__device__ float g_f1a[BD * NN * 128];
__device__ float g_f1b[BD * NN * 128];
__device__ float g_f0a[BD * 128];
__device__ float g_f0b[BD * 128];
__device__ float g_r1[BD * 2 * 128];
__device__ float g_r2[BD * NN * 2 * 128];
__device__ float g_P[BD * NN * OO];
__device__ float g_Q[BD * NN * OO];

__device__ __forceinline__ float sigmoidf_(float x) {
    return 1.0f / (1.0f + __expf(-x));
}

__device__ __forceinline__ uint32_t smem_u32(const void* p) {
    uint32_t a;
    asm("{ .reg .u64 t; cvta.to.shared.u64 t, %1; cvt.u32.u64 %0, t; }"
        : "=r"(a) : "l"(p));
    return a;
}
__device__ __forceinline__ void cpa16(uint32_t dst, const void* src) {
    asm volatile("cp.async.cg.shared.global [%0], [%1], 16;" :: "r"(dst), "l"(src));
}
__device__ __forceinline__ void cpcommit() {
    asm volatile("cp.async.commit_group;" ::: "memory");
}
__device__ __forceinline__ void cpwait1() {
    asm volatile("cp.async.wait_group 1;" ::: "memory");
}
__device__ __forceinline__ void cpwait0() {
    asm volatile("cp.async.wait_group 0;" ::: "memory");
}

#define MMA_B16(d, a, b) \
    asm volatile( \
        "mma.sync.aligned.m16n8k16.row.col.f32.bf16.bf16.f32 " \
        "{%0,%1,%2,%3}, {%4,%5,%6,%7}, {%8,%9}, {%0,%1,%2,%3};" \
        : "+f"((d)[0]), "+f"((d)[1]), "+f"((d)[2]), "+f"((d)[3]) \
        : "r"((a)[0]), "r"((a)[1]), "r"((a)[2]), "r"((a)[3]), \
          "r"((b)[0]), "r"((b)[1]))

// ---------------------------------------------------------------------------
// Conversions
// ---------------------------------------------------------------------------
__global__ void k_xconv(const float4* __restrict__ x,
                        __nv_bfloat16* __restrict__ h,
                        __nv_bfloat16* __restrict__ l, int n4) {
    int idx = blockIdx.x * blockDim.x + threadIdx.x;
    if (idx >= n4) return;
    float4 v = x[idx];
    __nv_bfloat16 h0 = __float2bfloat16(v.x), h1 = __float2bfloat16(v.y);
    __nv_bfloat16 h2 = __float2bfloat16(v.z), h3 = __float2bfloat16(v.w);
    __nv_bfloat162* hp = (__nv_bfloat162*)(h + (size_t)idx * 4);
    __nv_bfloat162* lp = (__nv_bfloat162*)(l + (size_t)idx * 4);
    hp[0] = __nv_bfloat162(h0, h1);
    hp[1] = __nv_bfloat162(h2, h3);
    lp[0] = __nv_bfloat162(__float2bfloat16(v.x - __bfloat162float(h0)),
                           __float2bfloat16(v.y - __bfloat162float(h1)));
    lp[1] = __nv_bfloat162(__float2bfloat16(v.z - __bfloat162float(h2)),
                           __float2bfloat16(v.w - __bfloat162float(h3)));
}

// W scratch: [4][128 o][d2+8 k]: v0=Wb_h, v1=Wb_l, v2=Wd_h, v3=Wd_l.
__global__ void k_wconv(const float* __restrict__ Wb, const float* __restrict__ Wd,
                        __nv_bfloat16* __restrict__ ws, int d2) {
    int o = blockIdx.x;
    int wr = d2 + 8;
    for (int k = threadIdx.x; k < d2; k += blockDim.x) {
        float vb = Wb[(size_t)k * OO + o];
        float vd = Wd[(size_t)k * OO + o];
        __nv_bfloat16 hb = __float2bfloat16(vb);
        __nv_bfloat16 lb = __float2bfloat16(vb - __bfloat162float(hb));
        __nv_bfloat16 hd = __float2bfloat16(vd);
        __nv_bfloat16 ld2 = __float2bfloat16(vd - __bfloat162float(hd));
        ws[(size_t)(0 * 128 + o) * wr + k] = hb;
        ws[(size_t)(1 * 128 + o) * wr + k] = lb;
        ws[(size_t)(2 * 128 + o) * wr + k] = hd;
        ws[(size_t)(3 * 128 + o) * wr + k] = ld2;
    }
}

// ---------------------------------------------------------------------------
// Reductions
// ---------------------------------------------------------------------------
__global__ void k_reduce1(const float* __restrict__ f1, float* __restrict__ r1, int d1) {
    int b = blockIdx.x;
    int k = threadIdx.x;
    if (k >= d1) return;
    const float* p = f1 + (size_t)b * NN * d1 + k;
    float mx = -1e30f, mn = 1e30f;
    for (int i = 0; i < NN; i++) {
        float v = p[(size_t)i * d1];
        mx = fmaxf(mx, v);
        mn = fminf(mn, v);
    }
    r1[b * 2 * d1 + k] = mx;
    r1[b * 2 * d1 + d1 + k] = mn;
}

__global__ void k_reduce2b(const __nv_bfloat16* __restrict__ Xh,
                           const __nv_bfloat16* __restrict__ Xl,
                           float* __restrict__ r2, int d2) {
    int bi = blockIdx.x;
    int i = bi & 255;
    int k = threadIdx.x;
    if (k >= d2) return;
    const __nv_bfloat16* ph = Xh + (size_t)bi * NN * d2 + k;
    const __nv_bfloat16* pl = Xl + (size_t)bi * NN * d2 + k;
    float mx = -1e30f, mn = 1e30f;
    for (int j = 0; j < NN; j++) {
        float v = __bfloat162float(ph[(size_t)j * d2]) +
                  __bfloat162float(pl[(size_t)j * d2]);
        float vm = (j == i) ? 0.0f : v;
        float vn = (j == i) ? 1.0f : v;
        mx = fmaxf(mx, vm);
        mn = fminf(mn, vn);
    }
    r2[(size_t)bi * 2 * d2 + k] = mx;
    r2[(size_t)bi * 2 * d2 + d2 + k] = mn;
}

// ---------------------------------------------------------------------------
// Order 0
// ---------------------------------------------------------------------------
__global__ void k_ord0(const float* __restrict__ f0, const float* __restrict__ r1,
                       const float* __restrict__ W, const float* __restrict__ bias,
                       float* __restrict__ out, int d0, int d1) {
    __shared__ float sg[384];
    int b = blockIdx.x, t = threadIdx.x;
    for (int idx = t; idx < d0; idx += blockDim.x) sg[idx] = f0[b * d0 + idx];
    for (int idx = t; idx < 2 * d1; idx += blockDim.x) sg[d0 + idx] = r1[b * 2 * d1 + idx];
    __syncthreads();
    int K = d0 + 2 * d1;
    float acc = bias[t];
    for (int k = 0; k < K; k++) acc += sg[k] * W[k * OO + t];
    out[b * OO + t] = sigmoidf_(acc);
}

// ---------------------------------------------------------------------------
// Order 1: 16 rows per block
// ---------------------------------------------------------------------------
__global__ __launch_bounds__(128) void k_ord1(
    const float* __restrict__ f0, const float* __restrict__ f1,
    const float* __restrict__ r2,
    const float* __restrict__ W, const float* __restrict__ bias,
    float* __restrict__ out, int d0, int d1, int d2) {
    __shared__ float sg[16][512];
    int bi0 = blockIdx.x * 16;
    int b = bi0 / NN;
    int t = threadIdx.x;
    int K = d0 + d1 + 2 * d2;
    for (int r = 0; r < 16; r++) {
        int bi = bi0 + r;
        for (int idx = t; idx < d0; idx += 128) sg[r][idx] = f0[b * d0 + idx];
        for (int idx = t; idx < d1; idx += 128) sg[r][d0 + idx] = f1[(size_t)bi * d1 + idx];
        for (int idx = t; idx < 2 * d2; idx += 128)
            sg[r][d0 + d1 + idx] = r2[(size_t)bi * 2 * d2 + idx];
    }
    __syncthreads();
    float acc[16];
    float bv = bias[t];
#pragma unroll
    for (int r = 0; r < 16; r++) acc[r] = bv;
#pragma unroll 4
    for (int k = 0; k < K; k++) {
        float wv = __ldg(W + k * OO + t);
#pragma unroll
        for (int r = 0; r < 16; r++) acc[r] += sg[r][k] * wv;
    }
#pragma unroll
    for (int r = 0; r < 16; r++)
        out[(size_t)(bi0 + r) * OO + t] = sigmoidf_(acc[r]);
}

// ---------------------------------------------------------------------------
// P/Q precompute: 16 rows per block
// ---------------------------------------------------------------------------
__global__ __launch_bounds__(128) void k_pq(
    const float* __restrict__ f1, const float* __restrict__ W2,
    const float* __restrict__ b2,
    float* __restrict__ P, float* __restrict__ Q, int d1, int d2) {
    __shared__ float sf[16][128];
    int bi0 = blockIdx.x * 16;
    int t = threadIdx.x;
    for (int r = 0; r < 16; r++)
        for (int idx = t; idx < d1; idx += 128)
            sf[r][idx] = f1[(size_t)(bi0 + r) * d1 + idx];
    __syncthreads();
    const float* Wa = W2;
    const float* Wc = W2 + (size_t)(d1 + d2) * OO;
    float bv = b2[t];
    float pa[16], qa[16];
#pragma unroll
    for (int r = 0; r < 16; r++) { pa[r] = bv; qa[r] = 0.0f; }
#pragma unroll 4
    for (int k = 0; k < d1; k++) {
        float wa = __ldg(Wa + k * OO + t);
        float wc = __ldg(Wc + k * OO + t);
#pragma unroll
        for (int r = 0; r < 16; r++) {
            pa[r] += sf[r][k] * wa;
            qa[r] += sf[r][k] * wc;
        }
    }
#pragma unroll
    for (int r = 0; r < 16; r++) {
        P[(size_t)(bi0 + r) * OO + t] = pa[r];
        Q[(size_t)(bi0 + r) * OO + t] = qa[r];
    }
}

// ---------------------------------------------------------------------------
// Order 2 via mma.sync. Grid (1024 bi, 2 j-half). 512 threads, 16 warps (4x4).
// Block tile 128(j) x 128(o); warp tile 32x32; thread acc 2x4x4 m16n8 tiles.
// W: 4 variants resident in smem [o][d2+8] bf16 (from g_ws via cp.async).
// X: chunks of 32 k, (h,l) variants, rows at XRS=112B stride (conflict-free),
// 3-stage cp.async pipeline: wait -> sync -> stage(c+2) -> compute(c).
// ---------------------------------------------------------------------------
template <int D2>
__device__ __forceinline__ void stageX(uint32_t dstBase,
                                       const __nv_bfloat16* __restrict__ Xh,
                                       const __nv_bfloat16* __restrict__ Xl,
                                       int chunk, int bi, int b, int i, int jb, int t) {
    constexpr int NC2 = D2 / 32;
    const bool sa = chunk < NC2;
    const int kc = (sa ? chunk : chunk - NC2) * 32;
#pragma unroll
    for (int s = 0; s < 2; s++) {
        int idx = t + s * 512;          // 0..1023
        int v = idx >> 9;               // variant (h/l)
        int r = (idx >> 2) & 127;       // row
        int u = idx & 3;                // 16B unit
        const __nv_bfloat16* src = v ? Xl : Xh;
        size_t row = sa ? ((size_t)bi * NN + (jb + r))
                        : ((size_t)(b * NN + jb + r) * NN + i);
        const void* gp = (const char*)(src + row * D2 + kc) + u * 16;
        cpa16(dstBase + v * (128 * XRS) + r * XRS + u * 16, gp);
    }
}

template <int D2>
__device__ __forceinline__ void computeChunk(
    const char* __restrict__ sW, const char* __restrict__ sXs,
    bool sa, int kc, int wm, int wn, int g, int tig, float acc[2][4][4]) {
    constexpr int WR2 = (D2 + 8) * 2;
    const char* wh = sW + (size_t)(sa ? 0 : 2) * (128 * WR2);
    const char* wl = sW + (size_t)(sa ? 1 : 3) * (128 * WR2);
    const char* xh = sXs;
    const char* xl = sXs + 128 * XRS;
#pragma unroll
    for (int ks = 0; ks < 2; ks++) {
        int kg = kc + ks * 16;
        int c0 = (ks * 16 + 2 * tig) * 2;
        int c8 = c0 + 16;
        uint32_t bwh[4][2], bwl[4][2];
#pragma unroll
        for (int nt = 0; nt < 4; nt++) {
            int orow = wn * 32 + nt * 8 + g;
            const char* ph = wh + orow * WR2 + (kg + 2 * tig) * 2;
            const char* pl = wl + orow * WR2 + (kg + 2 * tig) * 2;
            bwh[nt][0] = *(const uint32_t*)(ph);
            bwh[nt][1] = *(const uint32_t*)(ph + 16);
            bwl[nt][0] = *(const uint32_t*)(pl);
            bwl[nt][1] = *(const uint32_t*)(pl + 16);
        }
#pragma unroll
        for (int mt = 0; mt < 2; mt++) {
            int r0 = wm * 32 + mt * 16 + g;
            uint32_t axh[4], axl[4];
            axh[0] = *(const uint32_t*)(xh + r0 * XRS + c0);
            axh[1] = *(const uint32_t*)(xh + (r0 + 8) * XRS + c0);
            axh[2] = *(const uint32_t*)(xh + r0 * XRS + c8);
            axh[3] = *(const uint32_t*)(xh + (r0 + 8) * XRS + c8);
            axl[0] = *(const uint32_t*)(xl + r0 * XRS + c0);
            axl[1] = *(const uint32_t*)(xl + (r0 + 8) * XRS + c0);
            axl[2] = *(const uint32_t*)(xl + r0 * XRS + c8);
            axl[3] = *(const uint32_t*)(xl + (r0 + 8) * XRS + c8);
#pragma unroll
            for (int nt = 0; nt < 4; nt++) {
                MMA_B16(acc[mt][nt], axh, bwh[nt]);
                MMA_B16(acc[mt][nt], axh, bwl[nt]);
                MMA_B16(acc[mt][nt], axl, bwh[nt]);
            }
        }
    }
}

template <int D2, bool F32OUT>
__global__ __launch_bounds__(512) void k_ord2m(
    const __nv_bfloat16* __restrict__ Xh, const __nv_bfloat16* __restrict__ Xl,
    const __nv_bfloat16* __restrict__ Ws,
    const float* __restrict__ P, const float* __restrict__ Q,
    float* __restrict__ outF,
    __nv_bfloat16* __restrict__ Oh, __nv_bfloat16* __restrict__ Ol) {
    constexpr int NCH = 2 * (D2 / 32);
    constexpr int WR2 = (D2 + 8) * 2;
    constexpr int WBYTES = 4 * 128 * WR2;
    constexpr int XSTAGE = 2 * 128 * XRS;
    extern __shared__ __align__(16) char smem[];
    char* sW = smem;
    char* sX = smem + WBYTES;
    float* sP = (float*)(smem + WBYTES + 3 * XSTAGE);

    int t = threadIdx.x;
    int bi = blockIdx.x, b = bi >> 8, i = bi & 255;
    int jb = blockIdx.y * 128;
    uint32_t sWu = smem_u32(smem);
    uint32_t sXu = sWu + WBYTES;

    // Stage W (linear copy; grouped with chunk 0).
    {
        constexpr int WU = WBYTES / 16;
        const char* wsrc = (const char*)Ws;
        for (int u = t; u < WU; u += 512) cpa16(sWu + u * 16, wsrc + u * 16);
    }
    stageX<D2>(sXu, Xh, Xl, 0, bi, b, i, jb, t);
    cpcommit();
    stageX<D2>(sXu + XSTAGE, Xh, Xl, 1, bi, b, i, jb, t);
    cpcommit();
    if (t < 128) sP[t] = P[(size_t)bi * OO + t];

    int lane = t & 31, warp = t >> 5;
    int g = lane >> 2, tig = lane & 3;
    int wm = warp >> 2, wn = warp & 3;

    float acc[2][4][4];
#pragma unroll
    for (int a = 0; a < 2; a++)
#pragma unroll
        for (int c = 0; c < 4; c++)
#pragma unroll
            for (int d = 0; d < 4; d++) acc[a][c][d] = 0.0f;

#pragma unroll 1
    for (int c = 0; c < NCH; c++) {
        if (c + 1 < NCH) cpwait1(); else cpwait0();
        __syncthreads();
        if (c + 2 < NCH) {
            stageX<D2>(sXu + ((c + 2) % 3) * XSTAGE, Xh, Xl, c + 2, bi, b, i, jb, t);
            cpcommit();
        }
        bool sa = c < NCH / 2;
        int kc = (sa ? c : c - NCH / 2) * 32;
        computeChunk<D2>(sW, sX + (c % 3) * XSTAGE, sa, kc, wm, wn, g, tig, acc);
    }

    // Epilogue.
#pragma unroll
    for (int mt = 0; mt < 2; mt++) {
        int jl = wm * 32 + mt * 16 + g;
#pragma unroll
        for (int half = 0; half < 2; half++) {
            int j = jb + jl + half * 8;
            size_t rowq = ((size_t)(b * NN) + j) * OO;
            size_t rowo = ((size_t)bi * NN + j) * OO;
#pragma unroll
            for (int nt = 0; nt < 4; nt++) {
                int c = wn * 32 + nt * 8 + tig * 2;
                float a0 = acc[mt][nt][half * 2 + 0];
                float a1 = acc[mt][nt][half * 2 + 1];
                float2 q = *(const float2*)(Q + rowq + c);
                float v0 = sigmoidf_(sP[c] + q.x + a0);
                float v1 = sigmoidf_(sP[c + 1] + q.y + a1);
                if (F32OUT) {
                    float2 ov; ov.x = v0; ov.y = v1;
                    *(float2*)(outF + rowo + c) = ov;
                } else {
                    __nv_bfloat16 h0 = __float2bfloat16(v0);
                    __nv_bfloat16 h1 = __float2bfloat16(v1);
                    *(__nv_bfloat162*)(Oh + rowo + c) = __nv_bfloat162(h0, h1);
                    *(__nv_bfloat162*)(Ol + rowo + c) = __nv_bfloat162(
                        __float2bfloat16(v0 - __bfloat162float(h0)),
                        __float2bfloat16(v1 - __bfloat162float(h1)));
                }
            }
        }
    }
}

// ---------------------------------------------------------------------------
// Host side
// ---------------------------------------------------------------------------
static inline size_t smem_ord2m(int d2) {
    return (size_t)4 * 128 * (d2 + 8) * 2 + 3 * (2 * 128 * XRS) + 512;
}

extern "C" void kernel_launch(void* const* d_in, const int* in_sizes, int n_in,
                              void* d_out, int out_size) {
    const float* x0 = (const float*)d_in[0];
    const float* x1 = (const float*)d_in[1];
    const float* x2 = (const float*)d_in[2];
    const float* Wt[3][3];
    const float* bt[3][3];
    for (int l = 0; l < 3; l++)
        for (int o = 0; o < 3; o++) {
            Wt[l][o] = (const float*)d_in[3 + l * 6 + o * 2];
            bt[l][o] = (const float*)d_in[3 + l * 6 + o * 2 + 1];
        }

    __nv_bfloat16 *h0, *l0, *h1, *l1, *ws;
    float *f1a, *f1b, *f0a, *f0b, *r1, *r2, *P, *Q;
    cudaGetSymbolAddress((void**)&h0, g_h0);
    cudaGetSymbolAddress((void**)&l0, g_l0);
    cudaGetSymbolAddress((void**)&h1, g_h1);
    cudaGetSymbolAddress((void**)&l1, g_l1);
    cudaGetSymbolAddress((void**)&ws, g_ws);
    cudaGetSymbolAddress((void**)&f1a, g_f1a);
    cudaGetSymbolAddress((void**)&f1b, g_f1b);
    cudaGetSymbolAddress((void**)&f0a, g_f0a);
    cudaGetSymbolAddress((void**)&f0b, g_f0b);
    cudaGetSymbolAddress((void**)&r1, g_r1);
    cudaGetSymbolAddress((void**)&r2, g_r2);
    cudaGetSymbolAddress((void**)&P, g_P);
    cudaGetSymbolAddress((void**)&Q, g_Q);

    float* out = (float*)d_out;
    float* o0_f = out;
    float* o1_f = out + BD * OO;
    float* o2_f = out + BD * OO + (size_t)BD * NN * OO;

    cudaFuncSetAttribute(k_ord2m<64, false>, cudaFuncAttributeMaxDynamicSharedMemorySize,
                         (int)smem_ord2m(64));
    cudaFuncSetAttribute(k_ord2m<128, false>, cudaFuncAttributeMaxDynamicSharedMemorySize,
                         (int)smem_ord2m(128));
    cudaFuncSetAttribute(k_ord2m<128, true>, cudaFuncAttributeMaxDynamicSharedMemorySize,
                         (int)smem_ord2m(128));

    // Convert x2 -> (h0, l0) once.                          (launch 0)
    {
        int n4 = BD * NN * NN * 64 / 4;
        k_xconv<<<(n4 + 255) / 256, 256>>>((const float4*)x2, h0, l0, n4);
    }

    // ---- Layer 0, reordered so ord2m<64> is the 4th launch (ncu target) ----
    {
        const float* Wb = Wt[0][2] + (size_t)64 * OO;
        const float* Wd = Wt[0][2] + (size_t)(2 * 64 + 64) * OO;
        k_wconv<<<128, 128>>>(Wb, Wd, ws, 64);                        // 1
        k_pq<<<BD * NN / 16, 128>>>(x1, Wt[0][2], bt[0][2], P, Q, 64, 64);  // 2
        dim3 grid(BD * NN, 2);
        k_ord2m<64, false><<<grid, 512, smem_ord2m(64)>>>(            // 3 <- profiled
            h0, l0, ws, P, Q, nullptr, h1, l1);
        k_reduce1<<<BD, 128>>>(x1, r1, 64);                           // 4
        k_reduce2b<<<BD * NN, 128>>>(h0, l0, r2, 64);                 // 5
        k_ord0<<<BD, 128>>>(x0, r1, Wt[0][0], bt[0][0], f0a, 32, 64); // 6
        k_ord1<<<BD * NN / 16, 128>>>(x0, x1, r2, Wt[0][1], bt[0][1], f1a,
                                      32, 64, 64);                    // 7
    }

    // ---- Layers 1 and 2 ----
    struct L {
        const float* f0;
        const float* f1;
        const __nv_bfloat16 *xh, *xl;
        float *o0, *o1;
        __nv_bfloat16 *oh, *ol;
        float* of;
    };
    L Ls[2] = {
        { f0a, f1a, h1, l1, f0b,  f1b,  h0, l0, nullptr },
        { f0b, f1b, h0, l0, o0_f, o1_f, nullptr, nullptr, o2_f },
    };

    for (int li = 0; li < 2; li++) {
        int l = li + 1;
        const L& a = Ls[li];
        const float* Wb = Wt[l][2] + (size_t)128 * OO;
        const float* Wd = Wt[l][2] + (size_t)(2 * 128 + 128) * OO;
        k_wconv<<<128, 128>>>(Wb, Wd, ws, 128);
        k_reduce1<<<BD, 128>>>(a.f1, r1, 128);
        k_reduce2b<<<BD * NN, 128>>>(a.xh, a.xl, r2, 128);
        k_ord0<<<BD, 128>>>(a.f0, r1, Wt[l][0], bt[l][0], a.o0, 128, 128);
        k_ord1<<<BD * NN / 16, 128>>>(a.f0, a.f1, r2, Wt[l][1], bt[l][1], a.o1,
                                      128, 128, 128);
        k_pq<<<BD * NN / 16, 128>>>(a.f1, Wt[l][2], bt[l][2], P, Q, 128, 128);
        dim3 grid(BD * NN, 2);
        if (l == 2)
            k_ord2m<128, true><<<grid, 512, smem_ord2m(128)>>>(
                a.xh, a.xl, ws, P, Q, a.of, nullptr, nullptr);
        else
            k_ord2m<128, false><<<grid, 512, smem_ord2m(128)>>>(
                a.xh, a.xl, ws, P, Q, nullptr, a.oh, a.ol);
    }
}

// round 13
// speedup vs baseline: 1.5334x; 1.0342x over previous
#include <cuda_runtime.h>
#include <cuda_bf16.h>
#include <cstdint>

// ---------------------------------------------------------------------------
// LogicMachine (breadth=2, minmax, exclude_self, sigmoid), 3 layers.
// B=4, n=256, O=128. Layer dims: L0 in = (32,64,64); L1/L2 in = (128,128,128).
//
// o2[b,i,j] = sigmoid( P[b,i] + Q[b,j] + f2[b,i,j]·Wb + f2[b,j,i]·Wd )
//   with P = f1·Wa + b2, Q = f1·Wc   (Wa/Wb/Wc/Wd = row-slices of W2)
//
// ord2 via mma.sync.m16n8k16.bf16. 3-term bf16 hi/lo compensation:
//   x·w ≈ xh·wh + xh·wl + xl·wh  (fp32 accumulate)
// f2 carried between layers as bf16 (hi,lo) pairs.
// R13: fragment loads via ldmatrix.x4 (64 LDS.32 -> 16 ldmatrix per chunk,
// attacking the measured L1=45% bottleneck).
// ---------------------------------------------------------------------------

#define BD 4
#define NN 256
#define OO 128
#define XRS 112   // X smem row stride in bytes (conflict-free for ldmatrix)

// Inter-layer buffers.
__device__ __nv_bfloat16 g_h0[(size_t)BD * NN * NN * 128];
__device__ __nv_bfloat16 g_l0[(size_t)BD * NN * NN * 128];
__device__ __nv_bfloat16 g_h1[(size_t)BD * NN * NN * 128];
__device__ __nv_bfloat16 g_l1[(size_t)BD * NN * NN * 128];
__device__ __nv_bfloat16 g_ws[4 * 128 * 136];       // W scratch [4][128][D2+8]
__device__ float g_f1a[BD * NN * 128];
__device__ float g_f1b[BD * NN * 128];
__device__ float g_f0a[BD * 128];
__device__ float g_f0b[BD * 128];
__device__ float g_r1[BD * 2 * 128];
__device__ float g_r2[BD * NN * 2 * 128];
__device__ float g_P[BD * NN * OO];
__device__ float g_Q[BD * NN * OO];

__device__ __forceinline__ float sigmoidf_(float x) {
    return 1.0f / (1.0f + __expf(-x));
}

__device__ __forceinline__ uint32_t smem_u32(const void* p) {
    uint32_t a;
    asm("{ .reg .u64 t; cvta.to.shared.u64 t, %1; cvt.u32.u64 %0, t; }"
        : "=r"(a) : "l"(p));
    return a;
}
__device__ __forceinline__ void cpa16(uint32_t dst, const void* src) {
    asm volatile("cp.async.cg.shared.global [%0], [%1], 16;" :: "r"(dst), "l"(src));
}
__device__ __forceinline__ void cpcommit() {
    asm volatile("cp.async.commit_group;" ::: "memory");
}
__device__ __forceinline__ void cpwait1() {
    asm volatile("cp.async.wait_group 1;" ::: "memory");
}
__device__ __forceinline__ void cpwait0() {
    asm volatile("cp.async.wait_group 0;" ::: "memory");
}

#define MMA_B16(d, a, b) \
    asm volatile( \
        "mma.sync.aligned.m16n8k16.row.col.f32.bf16.bf16.f32 " \
        "{%0,%1,%2,%3}, {%4,%5,%6,%7}, {%8,%9}, {%0,%1,%2,%3};" \
        : "+f"((d)[0]), "+f"((d)[1]), "+f"((d)[2]), "+f"((d)[3]) \
        : "r"((a)[0]), "r"((a)[1]), "r"((a)[2]), "r"((a)[3]), \
          "r"((b)[0]), "r"((b)[1]))

#define LDSM4(r, addr) \
    asm volatile("ldmatrix.sync.aligned.m8n8.x4.shared.b16 {%0,%1,%2,%3}, [%4];" \
        : "=r"((r)[0]), "=r"((r)[1]), "=r"((r)[2]), "=r"((r)[3]) \
        : "r"(addr))

// ---------------------------------------------------------------------------
// Conversions
// ---------------------------------------------------------------------------
__global__ void k_xconv(const float4* __restrict__ x,
                        __nv_bfloat16* __restrict__ h,
                        __nv_bfloat16* __restrict__ l, int n4) {
    int idx = blockIdx.x * blockDim.x + threadIdx.x;
    if (idx >= n4) return;
    float4 v = x[idx];
    __nv_bfloat16 h0 = __float2bfloat16(v.x), h1 = __float2bfloat16(v.y);
    __nv_bfloat16 h2 = __float2bfloat16(v.z), h3 = __float2bfloat16(v.w);
    __nv_bfloat162* hp = (__nv_bfloat162*)(h + (size_t)idx * 4);
    __nv_bfloat162* lp = (__nv_bfloat162*)(l + (size_t)idx * 4);
    hp[0] = __nv_bfloat162(h0, h1);
    hp[1] = __nv_bfloat162(h2, h3);
    lp[0] = __nv_bfloat162(__float2bfloat16(v.x - __bfloat162float(h0)),
                           __float2bfloat16(v.y - __bfloat162float(h1)));
    lp[1] = __nv_bfloat162(__float2bfloat16(v.z - __bfloat162float(h2)),
                           __float2bfloat16(v.w - __bfloat162float(h3)));
}

// W scratch: [4][128 o][d2+8 k]: v0=Wb_h, v1=Wb_l, v2=Wd_h, v3=Wd_l.
__global__ void k_wconv(const float* __restrict__ Wb, const float* __restrict__ Wd,
                        __nv_bfloat16* __restrict__ ws, int d2) {
    int o = blockIdx.x;
    int wr = d2 + 8;
    for (int k = threadIdx.x; k < d2; k += blockDim.x) {
        float vb = Wb[(size_t)k * OO + o];
        float vd = Wd[(size_t)k * OO + o];
        __nv_bfloat16 hb = __float2bfloat16(vb);
        __nv_bfloat16 lb = __float2bfloat16(vb - __bfloat162float(hb));
        __nv_bfloat16 hd = __float2bfloat16(vd);
        __nv_bfloat16 ld2 = __float2bfloat16(vd - __bfloat162float(hd));
        ws[(size_t)(0 * 128 + o) * wr + k] = hb;
        ws[(size_t)(1 * 128 + o) * wr + k] = lb;
        ws[(size_t)(2 * 128 + o) * wr + k] = hd;
        ws[(size_t)(3 * 128 + o) * wr + k] = ld2;
    }
}

// ---------------------------------------------------------------------------
// Reductions
// ---------------------------------------------------------------------------
__global__ void k_reduce1(const float* __restrict__ f1, float* __restrict__ r1, int d1) {
    int b = blockIdx.x;
    int k = threadIdx.x;
    if (k >= d1) return;
    const float* p = f1 + (size_t)b * NN * d1 + k;
    float mx = -1e30f, mn = 1e30f;
    for (int i = 0; i < NN; i++) {
        float v = p[(size_t)i * d1];
        mx = fmaxf(mx, v);
        mn = fminf(mn, v);
    }
    r1[b * 2 * d1 + k] = mx;
    r1[b * 2 * d1 + d1 + k] = mn;
}

__global__ void k_reduce2b(const __nv_bfloat16* __restrict__ Xh,
                           const __nv_bfloat16* __restrict__ Xl,
                           float* __restrict__ r2, int d2) {
    int bi = blockIdx.x;
    int i = bi & 255;
    int k = threadIdx.x;
    if (k >= d2) return;
    const __nv_bfloat16* ph = Xh + (size_t)bi * NN * d2 + k;
    const __nv_bfloat16* pl = Xl + (size_t)bi * NN * d2 + k;
    float mx = -1e30f, mn = 1e30f;
    for (int j = 0; j < NN; j++) {
        float v = __bfloat162float(ph[(size_t)j * d2]) +
                  __bfloat162float(pl[(size_t)j * d2]);
        float vm = (j == i) ? 0.0f : v;
        float vn = (j == i) ? 1.0f : v;
        mx = fmaxf(mx, vm);
        mn = fminf(mn, vn);
    }
    r2[(size_t)bi * 2 * d2 + k] = mx;
    r2[(size_t)bi * 2 * d2 + d2 + k] = mn;
}

// ---------------------------------------------------------------------------
// Order 0
// ---------------------------------------------------------------------------
__global__ void k_ord0(const float* __restrict__ f0, const float* __restrict__ r1,
                       const float* __restrict__ W, const float* __restrict__ bias,
                       float* __restrict__ out, int d0, int d1) {
    __shared__ float sg[384];
    int b = blockIdx.x, t = threadIdx.x;
    for (int idx = t; idx < d0; idx += blockDim.x) sg[idx] = f0[b * d0 + idx];
    for (int idx = t; idx < 2 * d1; idx += blockDim.x) sg[d0 + idx] = r1[b * 2 * d1 + idx];
    __syncthreads();
    int K = d0 + 2 * d1;
    float acc = bias[t];
    for (int k = 0; k < K; k++) acc += sg[k] * W[k * OO + t];
    out[b * OO + t] = sigmoidf_(acc);
}

// ---------------------------------------------------------------------------
// Order 1: 16 rows per block
// ---------------------------------------------------------------------------
__global__ __launch_bounds__(128) void k_ord1(
    const float* __restrict__ f0, const float* __restrict__ f1,
    const float* __restrict__ r2,
    const float* __restrict__ W, const float* __restrict__ bias,
    float* __restrict__ out, int d0, int d1, int d2) {
    __shared__ float sg[16][512];
    int bi0 = blockIdx.x * 16;
    int b = bi0 / NN;
    int t = threadIdx.x;
    int K = d0 + d1 + 2 * d2;
    for (int r = 0; r < 16; r++) {
        int bi = bi0 + r;
        for (int idx = t; idx < d0; idx += 128) sg[r][idx] = f0[b * d0 + idx];
        for (int idx = t; idx < d1; idx += 128) sg[r][d0 + idx] = f1[(size_t)bi * d1 + idx];
        for (int idx = t; idx < 2 * d2; idx += 128)
            sg[r][d0 + d1 + idx] = r2[(size_t)bi * 2 * d2 + idx];
    }
    __syncthreads();
    float acc[16];
    float bv = bias[t];
#pragma unroll
    for (int r = 0; r < 16; r++) acc[r] = bv;
#pragma unroll 4
    for (int k = 0; k < K; k++) {
        float wv = __ldg(W + k * OO + t);
#pragma unroll
        for (int r = 0; r < 16; r++) acc[r] += sg[r][k] * wv;
    }
#pragma unroll
    for (int r = 0; r < 16; r++)
        out[(size_t)(bi0 + r) * OO + t] = sigmoidf_(acc[r]);
}

// ---------------------------------------------------------------------------
// P/Q precompute: 16 rows per block
// ---------------------------------------------------------------------------
__global__ __launch_bounds__(128) void k_pq(
    const float* __restrict__ f1, const float* __restrict__ W2,
    const float* __restrict__ b2,
    float* __restrict__ P, float* __restrict__ Q, int d1, int d2) {
    __shared__ float sf[16][128];
    int bi0 = blockIdx.x * 16;
    int t = threadIdx.x;
    for (int r = 0; r < 16; r++)
        for (int idx = t; idx < d1; idx += 128)
            sf[r][idx] = f1[(size_t)(bi0 + r) * d1 + idx];
    __syncthreads();
    const float* Wa = W2;
    const float* Wc = W2 + (size_t)(d1 + d2) * OO;
    float bv = b2[t];
    float pa[16], qa[16];
#pragma unroll
    for (int r = 0; r < 16; r++) { pa[r] = bv; qa[r] = 0.0f; }
#pragma unroll 4
    for (int k = 0; k < d1; k++) {
        float wa = __ldg(Wa + k * OO + t);
        float wc = __ldg(Wc + k * OO + t);
#pragma unroll
        for (int r = 0; r < 16; r++) {
            pa[r] += sf[r][k] * wa;
            qa[r] += sf[r][k] * wc;
        }
    }
#pragma unroll
    for (int r = 0; r < 16; r++) {
        P[(size_t)(bi0 + r) * OO + t] = pa[r];
        Q[(size_t)(bi0 + r) * OO + t] = qa[r];
    }
}

// ---------------------------------------------------------------------------
// Order 2 via mma.sync + ldmatrix. Grid (1024 bi, 2 j-half). 512 thr, 16 warps.
// Block tile 128(j) x 128(o); warp tile 32x32; thread acc 2x4x4 m16n8 tiles.
// W: 4 variants in smem [o][d2+8]; X: 32-k chunks, (h,l) variants, XRS stride,
// 3-stage cp.async pipeline. Fragments loaded with ldmatrix.x4 (16/chunk/warp).
// ---------------------------------------------------------------------------
template <int D2>
__device__ __forceinline__ void stageX(uint32_t dstBase,
                                       const __nv_bfloat16* __restrict__ Xh,
                                       const __nv_bfloat16* __restrict__ Xl,
                                       int chunk, int bi, int b, int i, int jb, int t) {
    constexpr int NC2 = D2 / 32;
    const bool sa = chunk < NC2;
    const int kc = (sa ? chunk : chunk - NC2) * 32;
#pragma unroll
    for (int s = 0; s < 2; s++) {
        int idx = t + s * 512;          // 0..1023
        int v = idx >> 9;               // variant (h/l)
        int r = (idx >> 2) & 127;       // row
        int u = idx & 3;                // 16B unit
        const __nv_bfloat16* src = v ? Xl : Xh;
        size_t row = sa ? ((size_t)bi * NN + (jb + r))
                        : ((size_t)(b * NN + jb + r) * NN + i);
        const void* gp = (const char*)(src + row * D2 + kc) + u * 16;
        cpa16(dstBase + v * (128 * XRS) + r * XRS + u * 16, gp);
    }
}

template <int D2>
__device__ __forceinline__ void computeChunk(
    uint32_t sWu, uint32_t sXsu, bool sa, int kc,
    int wm, int wn, int lane, float acc[2][4][4]) {
    constexpr int WR2 = (D2 + 8) * 2;
    uint32_t whB = sWu + (uint32_t)(sa ? 0 : 2) * (128 * WR2);
    uint32_t wlB = sWu + (uint32_t)(sa ? 1 : 3) * (128 * WR2);
    uint32_t xhB = sXsu;
    uint32_t xlB = sXsu + 128 * XRS;

    int quad = lane >> 3, lrow = lane & 7;
    // A ldmatrix lane address component: groups = (rowhalf, khalf).
    uint32_t aoff = (uint32_t)(wm * 32 + (quad & 1) * 8 + lrow) * XRS +
                    (uint32_t)(quad >> 1) * 16;
    // B ldmatrix: groups = (nt-within-pair, khalf); row base for pair p adds 16.
    uint32_t brow = (uint32_t)(wn * 32 + (quad >> 1) * 8 + lrow);
    uint32_t bkoff = (uint32_t)(quad & 1) * 16;

#pragma unroll
    for (int ks = 0; ks < 2; ks++) {
        int kg = kc + ks * 16;
        uint32_t bwh[2][4], bwl[2][4];
#pragma unroll
        for (int p = 0; p < 2; p++) {
            uint32_t baddr = (brow + p * 16) * WR2 + (uint32_t)kg * 2 + bkoff;
            LDSM4(bwh[p], whB + baddr);
            LDSM4(bwl[p], wlB + baddr);
        }
#pragma unroll
        for (int mt = 0; mt < 2; mt++) {
            uint32_t aaddr = aoff + (uint32_t)(mt * 16) * XRS + (uint32_t)(ks * 32);
            uint32_t axh[4], axl[4];
            LDSM4(axh, xhB + aaddr);
            LDSM4(axl, xlB + aaddr);
#pragma unroll
            for (int nt = 0; nt < 4; nt++) {
                uint32_t bh[2] = { bwh[nt >> 1][(nt & 1) * 2],
                                   bwh[nt >> 1][(nt & 1) * 2 + 1] };
                uint32_t bl[2] = { bwl[nt >> 1][(nt & 1) * 2],
                                   bwl[nt >> 1][(nt & 1) * 2 + 1] };
                MMA_B16(acc[mt][nt], axh, bh);
                MMA_B16(acc[mt][nt], axh, bl);
                MMA_B16(acc[mt][nt], axl, bh);
            }
        }
    }
}

template <int D2, bool F32OUT>
__global__ __launch_bounds__(512) void k_ord2m(
    const __nv_bfloat16* __restrict__ Xh, const __nv_bfloat16* __restrict__ Xl,
    const __nv_bfloat16* __restrict__ Ws,
    const float* __restrict__ P, const float* __restrict__ Q,
    float* __restrict__ outF,
    __nv_bfloat16* __restrict__ Oh, __nv_bfloat16* __restrict__ Ol) {
    constexpr int NCH = 2 * (D2 / 32);
    constexpr int WR2 = (D2 + 8) * 2;
    constexpr int WBYTES = 4 * 128 * WR2;
    constexpr int XSTAGE = 2 * 128 * XRS;
    extern __shared__ __align__(16) char smem[];
    float* sP = (float*)(smem + WBYTES + 3 * XSTAGE);

    int t = threadIdx.x;
    int bi = blockIdx.x, b = bi >> 8, i = bi & 255;
    int jb = blockIdx.y * 128;
    uint32_t sWu = smem_u32(smem);
    uint32_t sXu = sWu + WBYTES;

    // Stage W (linear copy; grouped with chunk 0).
    {
        constexpr int WU = WBYTES / 16;
        const char* wsrc = (const char*)Ws;
        for (int u = t; u < WU; u += 512) cpa16(sWu + u * 16, wsrc + u * 16);
    }
    stageX<D2>(sXu, Xh, Xl, 0, bi, b, i, jb, t);
    cpcommit();
    stageX<D2>(sXu + XSTAGE, Xh, Xl, 1, bi, b, i, jb, t);
    cpcommit();
    if (t < 128) sP[t] = P[(size_t)bi * OO + t];

    int lane = t & 31, warp = t >> 5;
    int g = lane >> 2, tig = lane & 3;
    int wm = warp >> 2, wn = warp & 3;

    float acc[2][4][4];
#pragma unroll
    for (int a = 0; a < 2; a++)
#pragma unroll
        for (int c = 0; c < 4; c++)
#pragma unroll
            for (int d = 0; d < 4; d++) acc[a][c][d] = 0.0f;

#pragma unroll 1
    for (int c = 0; c < NCH; c++) {
        if (c + 1 < NCH) cpwait1(); else cpwait0();
        __syncthreads();
        if (c + 2 < NCH) {
            stageX<D2>(sXu + ((c + 2) % 3) * XSTAGE, Xh, Xl, c + 2, bi, b, i, jb, t);
            cpcommit();
        }
        bool sa = c < NCH / 2;
        int kc = (sa ? c : c - NCH / 2) * 32;
        computeChunk<D2>(sWu, sXu + (c % 3) * XSTAGE, sa, kc, wm, wn, lane, acc);
    }

    // Epilogue.
#pragma unroll
    for (int mt = 0; mt < 2; mt++) {
        int jl = wm * 32 + mt * 16 + g;
#pragma unroll
        for (int half = 0; half < 2; half++) {
            int j = jb + jl + half * 8;
            size_t rowq = ((size_t)(b * NN) + j) * OO;
            size_t rowo = ((size_t)bi * NN + j) * OO;
#pragma unroll
            for (int nt = 0; nt < 4; nt++) {
                int c = wn * 32 + nt * 8 + tig * 2;
                float a0 = acc[mt][nt][half * 2 + 0];
                float a1 = acc[mt][nt][half * 2 + 1];
                float2 q = *(const float2*)(Q + rowq + c);
                float v0 = sigmoidf_(sP[c] + q.x + a0);
                float v1 = sigmoidf_(sP[c + 1] + q.y + a1);
                if (F32OUT) {
                    float2 ov; ov.x = v0; ov.y = v1;
                    *(float2*)(outF + rowo + c) = ov;
                } else {
                    __nv_bfloat16 h0 = __float2bfloat16(v0);
                    __nv_bfloat16 h1 = __float2bfloat16(v1);
                    *(__nv_bfloat162*)(Oh + rowo + c) = __nv_bfloat162(h0, h1);
                    *(__nv_bfloat162*)(Ol + rowo + c) = __nv_bfloat162(
                        __float2bfloat16(v0 - __bfloat162float(h0)),
                        __float2bfloat16(v1 - __bfloat162float(h1)));
                }
            }
        }
    }
}

// ---------------------------------------------------------------------------
// Host side
// ---------------------------------------------------------------------------
static inline size_t smem_ord2m(int d2) {
    return (size_t)4 * 128 * (d2 + 8) * 2 + 3 * (2 * 128 * XRS) + 512;
}

extern "C" void kernel_launch(void* const* d_in, const int* in_sizes, int n_in,
                              void* d_out, int out_size) {
    const float* x0 = (const float*)d_in[0];
    const float* x1 = (const float*)d_in[1];
    const float* x2 = (const float*)d_in[2];
    const float* Wt[3][3];
    const float* bt[3][3];
    for (int l = 0; l < 3; l++)
        for (int o = 0; o < 3; o++) {
            Wt[l][o] = (const float*)d_in[3 + l * 6 + o * 2];
            bt[l][o] = (const float*)d_in[3 + l * 6 + o * 2 + 1];
        }

    __nv_bfloat16 *h0, *l0, *h1, *l1, *ws;
    float *f1a, *f1b, *f0a, *f0b, *r1, *r2, *P, *Q;
    cudaGetSymbolAddress((void**)&h0, g_h0);
    cudaGetSymbolAddress((void**)&l0, g_l0);
    cudaGetSymbolAddress((void**)&h1, g_h1);
    cudaGetSymbolAddress((void**)&l1, g_l1);
    cudaGetSymbolAddress((void**)&ws, g_ws);
    cudaGetSymbolAddress((void**)&f1a, g_f1a);
    cudaGetSymbolAddress((void**)&f1b, g_f1b);
    cudaGetSymbolAddress((void**)&f0a, g_f0a);
    cudaGetSymbolAddress((void**)&f0b, g_f0b);
    cudaGetSymbolAddress((void**)&r1, g_r1);
    cudaGetSymbolAddress((void**)&r2, g_r2);
    cudaGetSymbolAddress((void**)&P, g_P);
    cudaGetSymbolAddress((void**)&Q, g_Q);

    float* out = (float*)d_out;
    float* o0_f = out;
    float* o1_f = out + BD * OO;
    float* o2_f = out + BD * OO + (size_t)BD * NN * OO;

    cudaFuncSetAttribute(k_ord2m<64, false>, cudaFuncAttributeMaxDynamicSharedMemorySize,
                         (int)smem_ord2m(64));
    cudaFuncSetAttribute(k_ord2m<128, false>, cudaFuncAttributeMaxDynamicSharedMemorySize,
                         (int)smem_ord2m(128));
    cudaFuncSetAttribute(k_ord2m<128, true>, cudaFuncAttributeMaxDynamicSharedMemorySize,
                         (int)smem_ord2m(128));

    // Convert x2 -> (h0, l0) once.                          (launch 0)
    {
        int n4 = BD * NN * NN * 64 / 4;
        k_xconv<<<(n4 + 255) / 256, 256>>>((const float4*)x2, h0, l0, n4);
    }

    // ---- Layer 0, ordered so ord2m<64> is the 4th launch (ncu target) ----
    {
        const float* Wb = Wt[0][2] + (size_t)64 * OO;
        const float* Wd = Wt[0][2] + (size_t)(2 * 64 + 64) * OO;
        k_wconv<<<128, 128>>>(Wb, Wd, ws, 64);                        // 1
        k_pq<<<BD * NN / 16, 128>>>(x1, Wt[0][2], bt[0][2], P, Q, 64, 64);  // 2
        dim3 grid(BD * NN, 2);
        k_ord2m<64, false><<<grid, 512, smem_ord2m(64)>>>(            // 3 <- profiled
            h0, l0, ws, P, Q, nullptr, h1, l1);
        k_reduce1<<<BD, 128>>>(x1, r1, 64);                           // 4
        k_reduce2b<<<BD * NN, 128>>>(h0, l0, r2, 64);                 // 5
        k_ord0<<<BD, 128>>>(x0, r1, Wt[0][0], bt[0][0], f0a, 32, 64); // 6
        k_ord1<<<BD * NN / 16, 128>>>(x0, x1, r2, Wt[0][1], bt[0][1], f1a,
                                      32, 64, 64);                    // 7
    }

    // ---- Layers 1 and 2 ----
    struct L {
        const float* f0;
        const float* f1;
        const __nv_bfloat16 *xh, *xl;
        float *o0, *o1;
        __nv_bfloat16 *oh, *ol;
        float* of;
    };
    L Ls[2] = {
        { f0a, f1a, h1, l1, f0b,  f1b,  h0, l0, nullptr },
        { f0b, f1b, h0, l0, o0_f, o1_f, nullptr, nullptr, o2_f },
    };

    for (int li = 0; li < 2; li++) {
        int l = li + 1;
        const L& a = Ls[li];
        const float* Wb = Wt[l][2] + (size_t)128 * OO;
        const float* Wd = Wt[l][2] + (size_t)(2 * 128 + 128) * OO;
        k_wconv<<<128, 128>>>(Wb, Wd, ws, 128);
        k_reduce1<<<BD, 128>>>(a.f1, r1, 128);
        k_reduce2b<<<BD * NN, 128>>>(a.xh, a.xl, r2, 128);
        k_ord0<<<BD, 128>>>(a.f0, r1, Wt[l][0], bt[l][0], a.o0, 128, 128);
        k_ord1<<<BD * NN / 16, 128>>>(a.f0, a.f1, r2, Wt[l][1], bt[l][1], a.o1,
                                      128, 128, 128);
        k_pq<<<BD * NN / 16, 128>>>(a.f1, Wt[l][2], bt[l][2], P, Q, 128, 128);
        dim3 grid(BD * NN, 2);
        if (l == 2)
            k_ord2m<128, true><<<grid, 512, smem_ord2m(128)>>>(
                a.xh, a.xl, ws, P, Q, a.of, nullptr, nullptr);
        else
            k_ord2m<128, false><<<grid, 512, smem_ord2m(128)>>>(
                a.xh, a.xl, ws, P, Q, nullptr, a.oh, a.ol);
    }
}